// round 15
// baseline (speedup 1.0000x reference)
#include <cuda_runtime.h>
#include <cstdint>

#define T_FRAMES 2000
#define HALF_T   1000
#define BATCH    64
#define CHANS    256
#define TLEN     200
#define RING     16
#define LN2      0.69314718055994530942f
#define DPB      64

// Scratch (__device__ globals: allocation-guard safe; zero-initialized once)
__device__ float g_lse_tr[BATCH * T_FRAMES];                     // [b][t]
__device__ float g_loss[BATCH];
__device__ uint4 g_E[(size_t)BATCH * T_FRAMES * 32];             // bf16 rows, 512B each
__device__ unsigned long long g_flag[(BATCH * T_FRAMES) / 8];    // 1 byte per (b,t); dp clears after use
__device__ unsigned g_cnt;                                       // monotonic across replays

__device__ __forceinline__ void cp16(uint32_t s, const void* g) {
    asm volatile("cp.async.cg.shared.global [%0], [%1], 16;" :: "r"(s), "l"(g));
}
__device__ __forceinline__ unsigned pack_bf16x2(float a, float b) {
    unsigned r;
    asm("cvt.rn.bf16x2.f32 %0, %1, %2;" : "=r"(r) : "f"(b), "f"(a));
    return r;
}
#define BF2LO(r) __uint_as_float((r) << 16)
#define BF2HI(r) __uint_as_float((r) & 0xffff0000u)

// wait until all 8 flag bytes of a group are set
__device__ __forceinline__ void spin8(const unsigned long long* p) {
    unsigned long long v;
    for (;;) {
        asm volatile("ld.acquire.gpu.global.b64 %0, [%1];" : "=l"(v) : "l"(p));
        if (v == 0x0101010101010101ull) return;
        __nanosleep(128);
    }
}
__device__ __forceinline__ void clr8(unsigned long long* p) {
    asm volatile("st.global.b64 [%0], %1;" :: "l"(p), "l"(0ull));
}

__global__ __launch_bounds__(256, 8) void fused_kernel(const float* __restrict__ inp,
                                                       const unsigned* __restrict__ tgtw,
                                                       float* __restrict__ out) {
    // gather role uses first 8KB; dp role uses 2x8KB rings + 1KB join area
    __shared__ __align__(16) unsigned char sraw[17416];

    if (blockIdx.x >= DPB) {
        // ==================== GATHER ROLE ====================
        // two production fronts: even tt -> t ascending from 0, odd tt -> descending from 1999
        int gbid = blockIdx.x - DPB;
        int warp = threadIdx.x >> 5, lane = threadIdx.x & 31;
        int oct = gbid & 7;
        int tt  = gbid >> 3;
        int t = (tt & 1) ? (T_FRAMES - 1 - (tt >> 1)) : (tt >> 1);
        int b = oct * 8 + warp;
        int r = t * BATCH + b;

        float* sm = reinterpret_cast<float*>(sraw) + warp * CHANS;

        const float4* base = reinterpret_cast<const float4*>(inp + (size_t)r * CHANS);
        float4 a = base[lane];
        float4 c = base[lane + 32];

        // target dtype auto-detect (JAX x64-off => int32); OR of odd words over
        // the first 512 32-bit words is zero iff little-endian int64 small values.
        unsigned orv = 0;
        #pragma unroll
        for (int k = 0; k < 8; k++) orv |= tgtw[lane * 2 + 1 + k * 64];
        #pragma unroll
        for (int o = 16; o; o >>= 1) orv |= __shfl_xor_sync(~0u, orv, o);
        int ws = (orv == 0) ? 2 : 1;

        // e = exp(x)/2. Logits ~N(0,1): no max subtraction, no overflow.
        float4 ea, ec;
        ea.x = __expf(a.x) * 0.5f;  ea.y = __expf(a.y) * 0.5f;
        ea.z = __expf(a.z) * 0.5f;  ea.w = __expf(a.w) * 0.5f;
        ec.x = __expf(c.x) * 0.5f;  ec.y = __expf(c.y) * 0.5f;
        ec.z = __expf(c.z) * 0.5f;  ec.w = __expf(c.w) * 0.5f;

        reinterpret_cast<float4*>(sm)[lane]      = ea;
        reinterpret_cast<float4*>(sm)[lane + 32] = ec;

        float sv = ((ea.x + ea.y) + (ea.z + ea.w)) + ((ec.x + ec.y) + (ec.z + ec.w));
        #pragma unroll
        for (int o = 16; o; o >>= 1) sv += __shfl_xor_sync(~0u, sv, o);
        if (lane == 0) g_lse_tr[b * T_FRAMES + t] = __logf(sv) + LN2;  // log(2*sum_e)
        __syncwarp();

        int idx[8];
        #pragma unroll
        for (int j = 0; j < 8; j++) {
            int l = lane * 7 + j;                 // slot 7 is padding (unused in DP)
            if (l > TLEN - 1) l = TLEN - 1;
            idx[j] = (int)tgtw[(b * TLEN + l) * ws];
        }
        uint4 pk;
        pk.x = pack_bf16x2(sm[idx[0]], sm[idx[1]]);
        pk.y = pack_bf16x2(sm[idx[2]], sm[idx[3]]);
        pk.z = pack_bf16x2(sm[idx[4]], sm[idx[5]]);
        pk.w = pack_bf16x2(sm[idx[6]], sm[idx[7]]);
        g_E[(size_t)(b * T_FRAMES + t) * 32 + lane] = pk;

        // publish: all lanes fence their writes, then lane0 sets the flag byte
        __threadfence();
        __syncwarp();
        if (lane == 0)
            *(volatile unsigned char*)((unsigned char*)g_flag + b * T_FRAMES + t) = 1;
        return;
    }

    // ==================== DP ROLE (warp0 fwd, warp1 bwd) ====================
    const int lane = threadIdx.x & 31;
    const int wid  = threadIdx.x >> 5;
    if (wid >= 2) return;                          // dp uses 64 threads; bar.sync 1,64 below
    const int b = blockIdx.x;

    uint4* ring  = reinterpret_cast<uint4*>(sraw) + wid * (RING * 32);   // 8KB each
    float* s_beta = reinterpret_cast<float*>(sraw + 16384);              // [7][32]
    int*   s_Xb   = reinterpret_cast<int*>(sraw + 16384 + 896);
    float* s_bls  = reinterpret_cast<float*>(sraw + 16384 + 896 + 128);

    const char* gb = (const char*)(g_E + (size_t)b * T_FRAMES * 32);
    unsigned long long* flg = g_flag + (b * T_FRAMES) / 8;               // 250 words
    uint32_t sb = (uint32_t)__cvta_generic_to_shared(ring);
    uint32_t so = lane * 16;

    // Prologue: wait for first 16 rows of this warp's front, then load them (4 groups).
    if (wid == 0) { spin8(flg + 0); spin8(flg + 1); }                    // rows 0..15
    else          { spin8(flg + 248); spin8(flg + 249); }                // rows 1984..1999
    #pragma unroll
    for (int g = 0; g < 4; g++) {
        #pragma unroll
        for (int rr = 0; rr < 4; rr++) {
            int i = g * 4 + rr;
            int row = wid ? (T_FRAMES - 1 - i) : i;
            cp16(sb + i * 512 + so, gb + (size_t)row * 512 + so);
        }
        asm volatile("cp.async.commit_group;");
    }
    asm volatile("cp.async.wait_group 0;");

    float p0, p1, p2, p3, p4, p5, p6;
    int   X = 0;
    float f;
    {
        uint4 v = ring[lane];
        if (wid == 0) {                      // alpha[0,l] = e_0[0]*[l==0]
            p0 = (lane == 0) ? BF2LO(v.x) : 0.0f;
            p1 = p2 = p3 = p4 = p5 = p6 = 0.0f;
            f  = (lane == 0) ? 0.0f : 1.0f;
        } else {                             // beta[1999,l] = e_1999[199]*[l==199] (lane28 slot3)
            p3 = (lane == 28) ? BF2HI(v.y) : 0.0f;
            p0 = p1 = p2 = p4 = p5 = p6 = 0.0f;
            f  = (lane == 31) ? 0.0f : 1.0f;
        }
    }

    if (wid == 0) {
        // ---------- FORWARD: frames 1..999 ----------
        #pragma unroll
        for (int t = 1; t < 8; t++) {
            uint4 v = ring[t * 32 + lane];
            float pin = __shfl_up_sync(~0u, p6, 1) * f;
            float e0 = BF2LO(v.x), e1 = BF2HI(v.x);
            float e2 = BF2LO(v.y), e3 = BF2HI(v.y);
            float e4 = BF2LO(v.z), e5 = BF2HI(v.z);
            float e6 = BF2LO(v.w);
            float n1 = e1 * (p1 + p0);
            float n2 = e2 * (p2 + p1);
            float n3 = e3 * (p3 + p2);
            float n4 = e4 * (p4 + p3);
            float n5 = e5 * (p5 + p4);
            float n6 = e6 * (p6 + p5);
            float n0 = e0 * (p0 + pin);
            p0 = n0; p1 = n1; p2 = n2; p3 = n3; p4 = n4; p5 = n5; p6 = n6;
        }
        for (int tb = 8; tb < HALF_T; tb += 8) {
            // prefetch rows tb+8..tb+15 into the half-ring just consumed
            if (tb + 8 < HALF_T) spin8(flg + (tb + 8) / 8);
            #pragma unroll
            for (int g = 0; g < 2; g++) {
                #pragma unroll
                for (int rr = 0; rr < 4; rr++) {
                    int rw = tb + 8 + g * 4 + rr;
                    if (rw < HALF_T)
                        cp16(sb + (rw & (RING - 1)) * 512 + so, gb + (size_t)rw * 512 + so);
                }
                asm volatile("cp.async.commit_group;");
            }
            asm volatile("cp.async.wait_group 2;");     // rows tb..tb+7 complete
            clr8(flg + (tb - 8) / 8);                   // rows tb-8..tb-1 fully consumed
            {   // renorm: lane-local power-of-2, factor from lane-1
                float m  = fmaxf(fmaxf(fmaxf(p0, p1), fmaxf(p2, p3)),
                                 fmaxf(fmaxf(p4, p5), p6));
                float m2 = fmaxf(m, 1.17549435e-38f);
                int k  = ((__float_as_int(m2) >> 23) & 255) - 127;
                int Xl = X + k;
                int Xp = __shfl_up_sync(~0u, Xl, 1);
                int d0 = (lane == 0) ? 0 : (Xp - Xl);
                int extra = d0 > 40 ? (d0 - 40) : 0;
                X = Xl + extra;
                int d = d0 - extra;
                if (d < -127) d = -127;
                float fn = __int_as_float((127 + d) << 23);
                f = (lane == 0) ? 0.0f : fn;
                int ex = -(k + extra);
                float psc = (ex < -126) ? 0.0f : __int_as_float((127 + ex) << 23);
                p0 *= psc; p1 *= psc; p2 *= psc; p3 *= psc;
                p4 *= psc; p5 *= psc; p6 *= psc;
            }
            int rbase = (tb & (RING - 1)) * 32 + lane;
            uint4 vcar = ring[rbase];
            #pragma unroll
            for (int u = 0; u < 8; u++) {
                uint4 v = vcar;
                if (u < 7) vcar = ring[rbase + (u + 1) * 32];
                float pin = __shfl_up_sync(~0u, p6, 1) * f;
                float e0 = BF2LO(v.x), e1 = BF2HI(v.x);
                float e2 = BF2LO(v.y), e3 = BF2HI(v.y);
                float e4 = BF2LO(v.z), e5 = BF2HI(v.z);
                float e6 = BF2LO(v.w);
                float n1 = e1 * (p1 + p0);
                float n2 = e2 * (p2 + p1);
                float n3 = e3 * (p3 + p2);
                float n4 = e4 * (p4 + p3);
                float n5 = e5 * (p5 + p4);
                float n6 = e6 * (p6 + p5);
                float n0 = e0 * (p0 + pin);
                p0 = n0; p1 = n1; p2 = n2; p3 = n3; p4 = n4; p5 = n5; p6 = n6;
            }
        }
        clr8(flg + 124);                     // rows 992..999
    } else {
        // ---------- BACKWARD: steps 1..999 (rows 1998..1000) ----------
        #pragma unroll
        for (int t = 1; t < 8; t++) {
            uint4 v = ring[t * 32 + lane];
            float pin = __shfl_down_sync(~0u, p0, 1) * f;
            float e0 = BF2LO(v.x), e1 = BF2HI(v.x);
            float e2 = BF2LO(v.y), e3 = BF2HI(v.y);
            float e4 = BF2LO(v.z), e5 = BF2HI(v.z);
            float e6 = BF2LO(v.w);
            float n0 = e0 * (p0 + p1);
            float n1 = e1 * (p1 + p2);
            float n2 = e2 * (p2 + p3);
            float n3 = e3 * (p3 + p4);
            float n4 = e4 * (p4 + p5);
            float n5 = e5 * (p5 + p6);
            float n6 = e6 * (p6 + pin);
            p0 = n0; p1 = n1; p2 = n2; p3 = n3; p4 = n4; p5 = n5; p6 = n6;
        }
        for (int tb = 8; tb < HALF_T; tb += 8) {
            // prefetch steps tb+8..tb+15 = rows 1984-tb..1991-tb
            if (tb + 8 < HALF_T) spin8(flg + (1984 - tb) / 8);
            #pragma unroll
            for (int g = 0; g < 2; g++) {
                #pragma unroll
                for (int rr = 0; rr < 4; rr++) {
                    int rw = tb + 8 + g * 4 + rr;
                    if (rw < HALF_T)
                        cp16(sb + (rw & (RING - 1)) * 512 + so,
                             gb + (size_t)(T_FRAMES - 1 - rw) * 512 + so);
                }
                asm volatile("cp.async.commit_group;");
            }
            asm volatile("cp.async.wait_group 2;");
            clr8(flg + (2000 - tb) / 8);     // actual rows 2000-tb..2007-tb consumed
            {   // renorm: factor from lane+1
                float m  = fmaxf(fmaxf(fmaxf(p0, p1), fmaxf(p2, p3)),
                                 fmaxf(fmaxf(p4, p5), p6));
                float m2 = fmaxf(m, 1.17549435e-38f);
                int k  = ((__float_as_int(m2) >> 23) & 255) - 127;
                int Xl = X + k;
                int Xn = __shfl_down_sync(~0u, Xl, 1);
                int d0 = (lane == 31) ? 0 : (Xn - Xl);
                int extra = d0 > 40 ? (d0 - 40) : 0;
                X = Xl + extra;
                int d = d0 - extra;
                if (d < -127) d = -127;
                float fn = __int_as_float((127 + d) << 23);
                f = (lane == 31) ? 0.0f : fn;
                int ex = -(k + extra);
                float psc = (ex < -126) ? 0.0f : __int_as_float((127 + ex) << 23);
                p0 *= psc; p1 *= psc; p2 *= psc; p3 *= psc;
                p4 *= psc; p5 *= psc; p6 *= psc;
            }
            int rbase = (tb & (RING - 1)) * 32 + lane;
            uint4 vcar = ring[rbase];
            #pragma unroll
            for (int u = 0; u < 8; u++) {
                uint4 v = vcar;
                if (u < 7) vcar = ring[rbase + (u + 1) * 32];
                float pin = __shfl_down_sync(~0u, p0, 1) * f;
                float e0 = BF2LO(v.x), e1 = BF2HI(v.x);
                float e2 = BF2LO(v.y), e3 = BF2HI(v.y);
                float e4 = BF2LO(v.z), e5 = BF2HI(v.z);
                float e6 = BF2LO(v.w);
                float n0 = e0 * (p0 + p1);
                float n1 = e1 * (p1 + p2);
                float n2 = e2 * (p2 + p3);
                float n3 = e3 * (p3 + p4);
                float n4 = e4 * (p4 + p5);
                float n5 = e5 * (p5 + p6);
                float n6 = e6 * (p6 + pin);
                p0 = n0; p1 = n1; p2 = n2; p3 = n3; p4 = n4; p5 = n5; p6 = n6;
            }
        }
        clr8(flg + 125);                     // actual rows 1000..1007
    }

    // per-warp lse partial (fwd: t 0..999, bwd: t 1000..1999); flags guarantee visibility
    const float* lseb = g_lse_tr + b * T_FRAMES + wid * HALF_T;
    float s = 0.0f;
    #pragma unroll 4
    for (int i = lane; i < HALF_T; i += 32) s += __ldcg(lseb + i);
    #pragma unroll
    for (int o = 16; o; o >>= 1) s += __shfl_xor_sync(~0u, s, o);

    if (wid == 1) {
        s_beta[0 * 32 + lane] = p0; s_beta[1 * 32 + lane] = p1; s_beta[2 * 32 + lane] = p2;
        s_beta[3 * 32 + lane] = p3; s_beta[4 * 32 + lane] = p4; s_beta[5 * 32 + lane] = p5;
        s_beta[6 * 32 + lane] = p6; s_Xb[lane] = X;
        if (lane == 0) *s_bls = s;
    }
    asm volatile("bar.sync 1, 64;" ::: "memory");

    if (wid == 0) {
        // join: beta_total = sum_l' beta[1000,l'] * (alpha[999,l'] + alpha[999,l'-1])
        float bb0 = s_beta[0 * 32 + lane], bb1 = s_beta[1 * 32 + lane], bb2 = s_beta[2 * 32 + lane];
        float bb3 = s_beta[3 * 32 + lane], bb4 = s_beta[4 * 32 + lane], bb5 = s_beta[5 * 32 + lane];
        float bb6 = s_beta[6 * 32 + lane];
        int   Xb  = s_Xb[lane];
        float a6p = __shfl_up_sync(~0u, p6, 1);          // alpha lane-1 slot6
        int   Xfp = __shfl_up_sync(~0u, X, 1);
        float Sa = bb0 * p0 + bb1 * (p1 + p0) + bb2 * (p2 + p1) + bb3 * (p3 + p2)
                 + bb4 * (p4 + p3) + bb5 * (p5 + p4) + bb6 * (p6 + p5);
        float C  = bb0 * a6p;
        float y1 = (Sa > 0.0f) ? __logf(Sa) + (float)(X + Xb) * LN2 : -1e30f;
        float y2 = (lane > 0 && C > 0.0f) ? __logf(C) + (float)(Xfp + Xb) * LN2 : -1e30f;
        float m = fmaxf(y1, y2);
        #pragma unroll
        for (int o = 16; o; o >>= 1) m = fmaxf(m, __shfl_xor_sync(~0u, m, o));
        float z = __expf(y1 - m) + __expf(y2 - m);
        #pragma unroll
        for (int o = 16; o; o >>= 1) z += __shfl_xor_sync(~0u, z, o);
        float beta_total = m + __logf(z) + (float)T_FRAMES * LN2;   // undo 2000x /2

        if (lane == 0) {
            float lossb = (s + *s_bls) - beta_total;
            asm volatile("st.global.cg.f32 [%0], %1;" :: "l"(g_loss + b), "f"(lossb));
            __threadfence();
            unsigned old = atomicAdd(&g_cnt, 1u);
            if ((old & 63u) == 63u) {                 // last dp block of THIS replay
                __threadfence();
                float tot = 0.0f;
                #pragma unroll 8
                for (int i = 0; i < BATCH; i++) tot += __ldcg(g_loss + i);
                out[0] = tot * (1.0f / BATCH);
            }
        }
    }
}

extern "C" void kernel_launch(void* const* d_in, const int* in_sizes, int n_in,
                              void* d_out, int out_size) {
    const float* inp = (const float*)d_in[0];        // [T, B, C] fp32
    const unsigned* tgt = (const unsigned*)d_in[1];  // [B, L] int32/int64 auto
    fused_kernel<<<DPB + T_FRAMES * 8, 256>>>(inp, tgt, (float*)d_out);
}

// round 17
// speedup vs baseline: 1.3112x; 1.3112x over previous
#include <cuda_runtime.h>
#include <cstdint>

#define T_FRAMES 2000
#define HALF_T   1000
#define BATCH    64
#define CHANS    256
#define TLEN     200
#define RING     32
#define LN2      0.69314718055994530942f

// Scratch (__device__ globals: allocation-guard safe)
__device__ float g_lse_tr[BATCH * T_FRAMES];                 // [b][t]
__device__ float g_loss[BATCH];
__device__ uint4 g_E[(size_t)BATCH * T_FRAMES * 32];         // bf16 rows, 512B each (65.5MB)
__device__ unsigned g_cnt;                                   // monotonic across replays

__device__ __forceinline__ void cp16(uint32_t s, const void* g) {
    asm volatile("cp.async.cg.shared.global [%0], [%1], 16;" :: "r"(s), "l"(g));
}
__device__ __forceinline__ unsigned pack_bf16x2(float a, float b) {
    unsigned r;
    asm("cvt.rn.bf16x2.f32 %0, %1, %2;" : "=r"(r) : "f"(b), "f"(a));
    return r;
}
#define BF2LO(r) __uint_as_float((r) << 16)
#define BF2HI(r) __uint_as_float((r) & 0xffff0000u)

// ---------------- Kernel 1: lse + gather, mirrored row-pair per warp ----------------
// Each warp handles rows (t0, b) and (1999-t0, b): 4 independent 128B loads in
// flight (2x MLP vs one-row version), index/dtype work amortized over 2 rows.
__global__ __launch_bounds__(256) void gather_lse(const float* __restrict__ inp,
                                                  const unsigned* __restrict__ tgtw) {
    __shared__ float sm[8][2][CHANS];                        // 16KB
    int warp = threadIdx.x >> 5, lane = threadIdx.x & 31;
    int t0 = blockIdx.x >> 3;                                // 0..999
    int b  = (blockIdx.x & 7) * 8 + warp;
    int t1 = T_FRAMES - 1 - t0;                              // mirrored row

    const float4* r0 = reinterpret_cast<const float4*>(inp + ((size_t)t0 * BATCH + b) * CHANS);
    const float4* r1 = reinterpret_cast<const float4*>(inp + ((size_t)t1 * BATCH + b) * CHANS);
    // issue all 4 loads up-front (MLP=4)
    float4 a0 = r0[lane];
    float4 c0 = r0[lane + 32];
    float4 a1 = r1[lane];
    float4 c1 = r1[lane + 32];

    // target dtype auto-detect (JAX x64-off => int32); OR of odd 32-bit words
    // over the first 512 words is zero iff little-endian int64 with small values.
    unsigned orv = 0;
    #pragma unroll
    for (int k = 0; k < 8; k++) orv |= tgtw[lane * 2 + 1 + k * 64];
    #pragma unroll
    for (int o = 16; o; o >>= 1) orv |= __shfl_xor_sync(~0u, orv, o);
    int ws = (orv == 0) ? 2 : 1;

    int idx[8];
    #pragma unroll
    for (int j = 0; j < 8; j++) {
        int l = lane * 7 + j;                                // slot 7 is padding
        if (l > TLEN - 1) l = TLEN - 1;
        idx[j] = (int)tgtw[(b * TLEN + l) * ws];             // L2-hits across blocks
    }

    // e = exp(x)/2. Logits ~N(0,1): no max subtraction needed, no overflow.
    float4 ea0, ec0, ea1, ec1;
    ea0.x = __expf(a0.x) * 0.5f;  ea0.y = __expf(a0.y) * 0.5f;
    ea0.z = __expf(a0.z) * 0.5f;  ea0.w = __expf(a0.w) * 0.5f;
    ec0.x = __expf(c0.x) * 0.5f;  ec0.y = __expf(c0.y) * 0.5f;
    ec0.z = __expf(c0.z) * 0.5f;  ec0.w = __expf(c0.w) * 0.5f;
    ea1.x = __expf(a1.x) * 0.5f;  ea1.y = __expf(a1.y) * 0.5f;
    ea1.z = __expf(a1.z) * 0.5f;  ea1.w = __expf(a1.w) * 0.5f;
    ec1.x = __expf(c1.x) * 0.5f;  ec1.y = __expf(c1.y) * 0.5f;
    ec1.z = __expf(c1.z) * 0.5f;  ec1.w = __expf(c1.w) * 0.5f;

    reinterpret_cast<float4*>(sm[warp][0])[lane]      = ea0;
    reinterpret_cast<float4*>(sm[warp][0])[lane + 32] = ec0;
    reinterpret_cast<float4*>(sm[warp][1])[lane]      = ea1;
    reinterpret_cast<float4*>(sm[warp][1])[lane + 32] = ec1;

    // two interleaved lse reductions
    float s0 = ((ea0.x + ea0.y) + (ea0.z + ea0.w)) + ((ec0.x + ec0.y) + (ec0.z + ec0.w));
    float s1 = ((ea1.x + ea1.y) + (ea1.z + ea1.w)) + ((ec1.x + ec1.y) + (ec1.z + ec1.w));
    #pragma unroll
    for (int o = 16; o; o >>= 1) {
        s0 += __shfl_xor_sync(~0u, s0, o);
        s1 += __shfl_xor_sync(~0u, s1, o);
    }
    if (lane == 0) {
        g_lse_tr[b * T_FRAMES + t0] = __logf(s0) + LN2;      // log(2*sum_e)
        g_lse_tr[b * T_FRAMES + t1] = __logf(s1) + LN2;
    }
    __syncwarp();

    const float* row0 = sm[warp][0];
    const float* row1 = sm[warp][1];
    uint4 pk0, pk1;
    pk0.x = pack_bf16x2(row0[idx[0]], row0[idx[1]]);
    pk0.y = pack_bf16x2(row0[idx[2]], row0[idx[3]]);
    pk0.z = pack_bf16x2(row0[idx[4]], row0[idx[5]]);
    pk0.w = pack_bf16x2(row0[idx[6]], row0[idx[7]]);
    pk1.x = pack_bf16x2(row1[idx[0]], row1[idx[1]]);
    pk1.y = pack_bf16x2(row1[idx[2]], row1[idx[3]]);
    pk1.z = pack_bf16x2(row1[idx[4]], row1[idx[5]]);
    pk1.w = pack_bf16x2(row1[idx[6]], row1[idx[7]]);
    g_E[(size_t)(b * T_FRAMES + t0) * 32 + lane] = pk0;
    g_E[(size_t)(b * T_FRAMES + t1) * 32 + lane] = pk1;
}

// ---------------- Kernel 2: meet-in-the-middle DP (warp0 fwd, warp1 bwd) + finisher ----------------
__global__ __launch_bounds__(64) void dp_kernel(float* __restrict__ out) {
    __shared__ __align__(16) uint4 ring2[2][RING * 32];      // 2 x 16KB
    __shared__ float s_beta[7][32];
    __shared__ int   s_Xb[32];
    __shared__ float s_bls;
    const int lane = threadIdx.x & 31;
    const int wid  = threadIdx.x >> 5;
    const int b = blockIdx.x;
    const char* gb = (const char*)(g_E + (size_t)b * T_FRAMES * 32);
    uint32_t sb = (uint32_t)__cvta_generic_to_shared(ring2[wid]);
    uint32_t so = lane * 16;

    // Prologue: steps 0..31. fwd reads row i, bwd reads row 1999-i into slot i.
    #pragma unroll
    for (int g = 0; g < 8; g++) {
        #pragma unroll
        for (int rr = 0; rr < 4; rr++) {
            int i = g * 4 + rr;
            int row = wid ? (T_FRAMES - 1 - i) : i;
            cp16(sb + i * 512 + so, gb + (size_t)row * 512 + so);
        }
        asm volatile("cp.async.commit_group;");
    }
    asm volatile("cp.async.wait_group 0;");

    float p0, p1, p2, p3, p4, p5, p6;
    int   X = 0;
    float f;
    {
        uint4 v = ring2[wid][lane];
        if (wid == 0) {                      // alpha[0,l] = e_0[0]*[l==0]
            p0 = (lane == 0) ? BF2LO(v.x) : 0.0f;
            p1 = p2 = p3 = p4 = p5 = p6 = 0.0f;
            f  = (lane == 0) ? 0.0f : 1.0f;
        } else {                             // beta[1999,l] = e_1999[199]*[l==199] (lane28 slot3)
            p3 = (lane == 28) ? BF2HI(v.y) : 0.0f;
            p0 = p1 = p2 = p4 = p5 = p6 = 0.0f;
            f  = (lane == 31) ? 0.0f : 1.0f;
        }
    }

    if (wid == 0) {
        // ---------- FORWARD: frames 1..999 ----------
        #pragma unroll
        for (int t = 1; t < 8; t++) {
            uint4 v = ring2[0][t * 32 + lane];
            float pin = __shfl_up_sync(~0u, p6, 1) * f;
            float e0 = BF2LO(v.x), e1 = BF2HI(v.x);
            float e2 = BF2LO(v.y), e3 = BF2HI(v.y);
            float e4 = BF2LO(v.z), e5 = BF2HI(v.z);
            float e6 = BF2LO(v.w);
            float n1 = e1 * (p1 + p0);
            float n2 = e2 * (p2 + p1);
            float n3 = e3 * (p3 + p2);
            float n4 = e4 * (p4 + p3);
            float n5 = e5 * (p5 + p4);
            float n6 = e6 * (p6 + p5);
            float n0 = e0 * (p0 + pin);
            p0 = n0; p1 = n1; p2 = n2; p3 = n3; p4 = n4; p5 = n5; p6 = n6;
        }
        uint4 vcar = ring2[0][8 * 32 + lane];
        for (int tb = 8; tb < HALF_T; tb += 8) {
            #pragma unroll
            for (int g = 0; g < 2; g++) {
                #pragma unroll
                for (int rr = 0; rr < 4; rr++) {
                    int rw = tb + 24 + g * 4 + rr;
                    if (rw < HALF_T)
                        cp16(sb + (rw & (RING - 1)) * 512 + so, gb + (size_t)rw * 512 + so);
                }
                asm volatile("cp.async.commit_group;");
            }
            asm volatile("cp.async.wait_group 3;");
            {   // renorm: lane-local power-of-2, factor from lane-1
                float m  = fmaxf(fmaxf(fmaxf(p0, p1), fmaxf(p2, p3)),
                                 fmaxf(fmaxf(p4, p5), p6));
                float m2 = fmaxf(m, 1.17549435e-38f);
                int k  = ((__float_as_int(m2) >> 23) & 255) - 127;
                int Xl = X + k;
                int Xp = __shfl_up_sync(~0u, Xl, 1);
                int d0 = (lane == 0) ? 0 : (Xp - Xl);
                int extra = d0 > 40 ? (d0 - 40) : 0;
                X = Xl + extra;
                int d = d0 - extra;
                if (d < -127) d = -127;
                float fn = __int_as_float((127 + d) << 23);
                f = (lane == 0) ? 0.0f : fn;
                int ex = -(k + extra);
                float psc = (ex < -126) ? 0.0f : __int_as_float((127 + ex) << 23);
                p0 *= psc; p1 *= psc; p2 *= psc; p3 *= psc;
                p4 *= psc; p5 *= psc; p6 *= psc;
            }
            int rbase = (tb & (RING - 1)) * 32 + lane;
            int rnext = (((tb + 8) & (RING - 1)) * 32) + lane;
            #pragma unroll
            for (int u = 0; u < 8; u++) {
                uint4 v = vcar;
                vcar = (u < 7) ? ring2[0][rbase + (u + 1) * 32] : ring2[0][rnext];
                float pin = __shfl_up_sync(~0u, p6, 1) * f;
                float e0 = BF2LO(v.x), e1 = BF2HI(v.x);
                float e2 = BF2LO(v.y), e3 = BF2HI(v.y);
                float e4 = BF2LO(v.z), e5 = BF2HI(v.z);
                float e6 = BF2LO(v.w);
                float n1 = e1 * (p1 + p0);
                float n2 = e2 * (p2 + p1);
                float n3 = e3 * (p3 + p2);
                float n4 = e4 * (p4 + p3);
                float n5 = e5 * (p5 + p4);
                float n6 = e6 * (p6 + p5);
                float n0 = e0 * (p0 + pin);
                p0 = n0; p1 = n1; p2 = n2; p3 = n3; p4 = n4; p5 = n5; p6 = n6;
            }
        }
    } else {
        // ---------- BACKWARD: steps 1..999 (rows 1998..1000) ----------
        #pragma unroll
        for (int t = 1; t < 8; t++) {
            uint4 v = ring2[1][t * 32 + lane];
            float pin = __shfl_down_sync(~0u, p0, 1) * f;
            float e0 = BF2LO(v.x), e1 = BF2HI(v.x);
            float e2 = BF2LO(v.y), e3 = BF2HI(v.y);
            float e4 = BF2LO(v.z), e5 = BF2HI(v.z);
            float e6 = BF2LO(v.w);
            float n0 = e0 * (p0 + p1);
            float n1 = e1 * (p1 + p2);
            float n2 = e2 * (p2 + p3);
            float n3 = e3 * (p3 + p4);
            float n4 = e4 * (p4 + p5);
            float n5 = e5 * (p5 + p6);
            float n6 = e6 * (p6 + pin);
            p0 = n0; p1 = n1; p2 = n2; p3 = n3; p4 = n4; p5 = n5; p6 = n6;
        }
        uint4 vcar = ring2[1][8 * 32 + lane];
        for (int tb = 8; tb < HALF_T; tb += 8) {
            #pragma unroll
            for (int g = 0; g < 2; g++) {
                #pragma unroll
                for (int rr = 0; rr < 4; rr++) {
                    int rw = tb + 24 + g * 4 + rr;
                    if (rw < HALF_T)
                        cp16(sb + (rw & (RING - 1)) * 512 + so,
                             gb + (size_t)(T_FRAMES - 1 - rw) * 512 + so);
                }
                asm volatile("cp.async.commit_group;");
            }
            asm volatile("cp.async.wait_group 3;");
            {   // renorm: factor from lane+1
                float m  = fmaxf(fmaxf(fmaxf(p0, p1), fmaxf(p2, p3)),
                                 fmaxf(fmaxf(p4, p5), p6));
                float m2 = fmaxf(m, 1.17549435e-38f);
                int k  = ((__float_as_int(m2) >> 23) & 255) - 127;
                int Xl = X + k;
                int Xn = __shfl_down_sync(~0u, Xl, 1);
                int d0 = (lane == 31) ? 0 : (Xn - Xl);
                int extra = d0 > 40 ? (d0 - 40) : 0;
                X = Xl + extra;
                int d = d0 - extra;
                if (d < -127) d = -127;
                float fn = __int_as_float((127 + d) << 23);
                f = (lane == 31) ? 0.0f : fn;
                int ex = -(k + extra);
                float psc = (ex < -126) ? 0.0f : __int_as_float((127 + ex) << 23);
                p0 *= psc; p1 *= psc; p2 *= psc; p3 *= psc;
                p4 *= psc; p5 *= psc; p6 *= psc;
            }
            int rbase = (tb & (RING - 1)) * 32 + lane;
            int rnext = (((tb + 8) & (RING - 1)) * 32) + lane;
            #pragma unroll
            for (int u = 0; u < 8; u++) {
                uint4 v = vcar;
                vcar = (u < 7) ? ring2[1][rbase + (u + 1) * 32] : ring2[1][rnext];
                float pin = __shfl_down_sync(~0u, p0, 1) * f;
                float e0 = BF2LO(v.x), e1 = BF2HI(v.x);
                float e2 = BF2LO(v.y), e3 = BF2HI(v.y);
                float e4 = BF2LO(v.z), e5 = BF2HI(v.z);
                float e6 = BF2LO(v.w);
                float n0 = e0 * (p0 + p1);
                float n1 = e1 * (p1 + p2);
                float n2 = e2 * (p2 + p3);
                float n3 = e3 * (p3 + p4);
                float n4 = e4 * (p4 + p5);
                float n5 = e5 * (p5 + p6);
                float n6 = e6 * (p6 + pin);
                p0 = n0; p1 = n1; p2 = n2; p3 = n3; p4 = n4; p5 = n5; p6 = n6;
            }
        }
    }

    // per-warp lse partial sum (fwd: t 0..999, bwd: t 1000..1999)
    const float* lseb = g_lse_tr + b * T_FRAMES + wid * HALF_T;
    float s = 0.0f;
    #pragma unroll 4
    for (int i = lane; i < HALF_T; i += 32) s += lseb[i];
    #pragma unroll
    for (int o = 16; o; o >>= 1) s += __shfl_xor_sync(~0u, s, o);

    if (wid == 1) {
        s_beta[0][lane] = p0; s_beta[1][lane] = p1; s_beta[2][lane] = p2;
        s_beta[3][lane] = p3; s_beta[4][lane] = p4; s_beta[5][lane] = p5;
        s_beta[6][lane] = p6; s_Xb[lane] = X;
        if (lane == 0) s_bls = s;
    }
    __syncthreads();

    if (wid == 0) {
        // join: beta_total = sum_l' beta[1000,l'] * (alpha[999,l'] + alpha[999,l'-1])
        float bb0 = s_beta[0][lane], bb1 = s_beta[1][lane], bb2 = s_beta[2][lane];
        float bb3 = s_beta[3][lane], bb4 = s_beta[4][lane], bb5 = s_beta[5][lane];
        float bb6 = s_beta[6][lane];
        int   Xb  = s_Xb[lane];
        float a6p = __shfl_up_sync(~0u, p6, 1);          // alpha lane-1 slot6
        int   Xfp = __shfl_up_sync(~0u, X, 1);
        float Sa = bb0 * p0 + bb1 * (p1 + p0) + bb2 * (p2 + p1) + bb3 * (p3 + p2)
                 + bb4 * (p4 + p3) + bb5 * (p5 + p4) + bb6 * (p6 + p5);
        float C  = bb0 * a6p;
        float y1 = (Sa > 0.0f) ? __logf(Sa) + (float)(X + Xb) * LN2 : -1e30f;
        float y2 = (lane > 0 && C > 0.0f) ? __logf(C) + (float)(Xfp + Xb) * LN2 : -1e30f;
        float m = fmaxf(y1, y2);
        #pragma unroll
        for (int o = 16; o; o >>= 1) m = fmaxf(m, __shfl_xor_sync(~0u, m, o));
        float z = __expf(y1 - m) + __expf(y2 - m);
        #pragma unroll
        for (int o = 16; o; o >>= 1) z += __shfl_xor_sync(~0u, z, o);
        float beta_total = m + __logf(z) + (float)T_FRAMES * LN2;   // undo 2000x /2

        if (lane == 0) {
            float lossb = (s + s_bls) - beta_total;
            asm volatile("st.global.cg.f32 [%0], %1;" :: "l"(g_loss + b), "f"(lossb));
            __threadfence();
            unsigned old = atomicAdd(&g_cnt, 1u);
            if ((old & 63u) == 63u) {                 // last dp block of THIS run
                __threadfence();
                float tot = 0.0f;
                #pragma unroll 8
                for (int i = 0; i < BATCH; i++) tot += __ldcg(g_loss + i);
                out[0] = tot * (1.0f / BATCH);
            }
        }
    }
}

extern "C" void kernel_launch(void* const* d_in, const int* in_sizes, int n_in,
                              void* d_out, int out_size) {
    const float* inp = (const float*)d_in[0];        // [T, B, C] fp32
    const unsigned* tgt = (const unsigned*)d_in[1];  // [B, L] int32/int64 auto
    gather_lse<<<(HALF_T) * 8, 256>>>(inp, tgt);     // 8000 blocks, 2 rows per warp
    dp_kernel<<<BATCH, 64>>>((float*)d_out);
}